// round 7
// baseline (speedup 1.0000x reference)
#include <cuda_runtime.h>
#include <cuda_bf16.h>
#include <cstddef>

#define LSEQ 768
#define DDIM 128
#define BATCH 16

__device__ __forceinline__ float4 ld4(const float* p) { return *(const float4*)p; }

static constexpr float INV_T = 0.08838834764831843f;  // 1/sqrt(128)

// ---------------------------------------------------------------------------
// Kernel 1: S = (Q K^T + local + D*fc_b) * INV_T  -> attn scratch.
// Tile 96x96, micro-tile 6x6 per thread = 2x2 CLIP(3) cells, so the local
// term is 4 thread-private reductions over the thread's own accumulators.
// Smem is d-major (transposed) so inner-loop reads are contiguous float2.
// ---------------------------------------------------------------------------
__global__ __launch_bounds__(256) void scores_kernel(
    const float* __restrict__ q, const float* __restrict__ k,
    const float* __restrict__ fc_w, const float* __restrict__ fc_b,
    float* __restrict__ attn)
{
    __shared__ float Qs[32][100];   // [d within chunk][row]
    __shared__ float Ks[32][100];

    const int b  = blockIdx.z;
    const int qt = blockIdx.y;
    const int kt = blockIdx.x;
    const int t  = threadIdx.x;
    const int ty = t >> 4;          // 0..15 -> q rows 6*ty..6*ty+5
    const int tx = t & 15;          // 0..15 -> k cols 6*tx..6*tx+5

    float acc[6][6] = {};

    const float* qbase = q + ((size_t)b * LSEQ + qt * 96) * DDIM;
    const float* kbase = k + ((size_t)b * LSEQ + kt * 96) * DDIM;

    for (int dc = 0; dc < 4; ++dc) {               // four 32-wide D chunks
        #pragma unroll
        for (int i = 0; i < 3; ++i) {              // 96 rows * 8 float4 = 768 per side
            int idx = t + i * 256;
            int row = idx >> 3;                    // 0..95
            int c4  = idx & 7;                     // 0..7
            float4 qv = ld4(qbase + row * DDIM + dc * 32 + c4 * 4);
            float4 kv = ld4(kbase + row * DDIM + dc * 32 + c4 * 4);
            Qs[c4 * 4 + 0][row] = qv.x;
            Qs[c4 * 4 + 1][row] = qv.y;
            Qs[c4 * 4 + 2][row] = qv.z;
            Qs[c4 * 4 + 3][row] = qv.w;
            Ks[c4 * 4 + 0][row] = kv.x;
            Ks[c4 * 4 + 1][row] = kv.y;
            Ks[c4 * 4 + 2][row] = kv.z;
            Ks[c4 * 4 + 3][row] = kv.w;
        }
        __syncthreads();

        #pragma unroll
        for (int d = 0; d < 32; ++d) {
            float2 q0 = *(const float2*)&Qs[d][6 * ty + 0];
            float2 q1 = *(const float2*)&Qs[d][6 * ty + 2];
            float2 q2 = *(const float2*)&Qs[d][6 * ty + 4];
            float2 k0 = *(const float2*)&Ks[d][6 * tx + 0];
            float2 k1 = *(const float2*)&Ks[d][6 * tx + 2];
            float2 k2 = *(const float2*)&Ks[d][6 * tx + 4];
            const float qv[6] = {q0.x, q0.y, q1.x, q1.y, q2.x, q2.y};
            const float kv[6] = {k0.x, k0.y, k1.x, k1.y, k2.x, k2.y};
            #pragma unroll
            for (int a = 0; a < 6; ++a)
                #pragma unroll
                for (int c = 0; c < 6; ++c)
                    acc[a][c] += qv[a] * kv[c];
        }
        __syncthreads();
    }

    // local term per 2x2 CLIP cells (thread-private)
    float w[9];
    #pragma unroll
    for (int i = 0; i < 9; ++i) w[i] = fc_w[i];
    const float base = 128.0f * fc_b[0];
    float loc[2][2];
    #pragma unroll
    for (int A = 0; A < 2; ++A)
        #pragma unroll
        for (int C = 0; C < 2; ++C) {
            float s = base;
            #pragma unroll
            for (int a = 0; a < 3; ++a)
                #pragma unroll
                for (int c = 0; c < 3; ++c)
                    s += w[a * 3 + c] * acc[3 * A + a][3 * C + c];
            loc[A][C] = s;
        }

    float* outp = attn + ((size_t)b * LSEQ + qt * 96 + 6 * ty) * LSEQ + kt * 96 + 6 * tx;
    #pragma unroll
    for (int r = 0; r < 6; ++r) {
        const int A = r / 3;
        #pragma unroll
        for (int c2 = 0; c2 < 3; ++c2) {
            float2 vv;
            vv.x = (acc[r][2 * c2 + 0] + loc[A][(2 * c2 + 0) / 3]) * INV_T;
            vv.y = (acc[r][2 * c2 + 1] + loc[A][(2 * c2 + 1) / 3]) * INV_T;
            *(float2*)(outp + (size_t)r * LSEQ + 2 * c2) = vv;
        }
    }
}

// ---------------------------------------------------------------------------
// Kernel 2: in-place row softmax over len_k = 768. One block per (b, q) row.
// ---------------------------------------------------------------------------
__global__ __launch_bounds__(256) void softmax_kernel(float* __restrict__ attn)
{
    const int row = blockIdx.x;
    float* p = attn + (size_t)row * LSEQ;
    const int t = threadIdx.x;

    __shared__ float red[8];

    float v0 = p[t], v1 = p[t + 256], v2 = p[t + 512];
    float m = fmaxf(fmaxf(v0, v1), v2);
    #pragma unroll
    for (int off = 16; off; off >>= 1)
        m = fmaxf(m, __shfl_xor_sync(0xffffffffu, m, off));
    if ((t & 31) == 0) red[t >> 5] = m;
    __syncthreads();
    m = fmaxf(fmaxf(fmaxf(red[0], red[1]), fmaxf(red[2], red[3])),
              fmaxf(fmaxf(red[4], red[5]), fmaxf(red[6], red[7])));
    __syncthreads();

    v0 = __expf(v0 - m); v1 = __expf(v1 - m); v2 = __expf(v2 - m);
    float s = v0 + v1 + v2;
    #pragma unroll
    for (int off = 16; off; off >>= 1)
        s += __shfl_xor_sync(0xffffffffu, s, off);
    if ((t & 31) == 0) red[t >> 5] = s;
    __syncthreads();
    s = (red[0] + red[1]) + (red[2] + red[3]) + (red[4] + red[5]) + (red[6] + red[7]);
    float inv = __frcp_rn(s);

    p[t]       = v0 * inv;
    p[t + 256] = v1 * inv;
    p[t + 512] = v2 * inv;
}

// ---------------------------------------------------------------------------
// Kernel 3: output = attn @ V.
// Tile 96 q-rows x 128 d-cols per block, thread = 6x8. K chunks of 32.
// attn tile stored k-major (transposed) -> contiguous float2 inner reads.
// ---------------------------------------------------------------------------
__global__ __launch_bounds__(256) void out_kernel(
    const float* __restrict__ attn, const float* __restrict__ v,
    float* __restrict__ out)
{
    __shared__ float As[32][100];   // [kk][q-row]
    __shared__ float Vs[32][132];   // [kk][d-col]

    const int b  = blockIdx.y;
    const int qt = blockIdx.x;
    const int t  = threadIdx.x;
    const int ty = t >> 4;          // 0..15 -> q rows 6*ty..6*ty+5
    const int tx = t & 15;          // 0..15 -> d cols 8*tx..8*tx+7

    float acc[6][8] = {};

    const float* arow = attn + ((size_t)b * LSEQ + qt * 96) * LSEQ;
    const float* vb   = v + (size_t)b * LSEQ * DDIM;

    for (int k0 = 0; k0 < LSEQ; k0 += 32) {
        // attn tile 96 rows x 32 cols -> transposed: 768 float4 / 256 thr
        #pragma unroll
        for (int i = 0; i < 3; ++i) {
            int idx = t + i * 256;
            int row = idx >> 3;                    // 0..95
            int c4  = idx & 7;                     // 0..7
            float4 av = ld4(arow + (size_t)row * LSEQ + k0 + c4 * 4);
            As[c4 * 4 + 0][row] = av.x;
            As[c4 * 4 + 1][row] = av.y;
            As[c4 * 4 + 2][row] = av.z;
            As[c4 * 4 + 3][row] = av.w;
        }
        // V tile 32 rows x 128 cols = 1024 float4 / 256 thr = 4 each
        #pragma unroll
        for (int i = 0; i < 4; ++i) {
            int idx = t + i * 256;
            int row = idx >> 5;                    // 0..31
            int c4  = idx & 31;
            *(float4*)&Vs[row][c4 * 4] = ld4(vb + (size_t)(k0 + row) * DDIM + c4 * 4);
        }
        __syncthreads();

        #pragma unroll
        for (int kk = 0; kk < 32; ++kk) {
            float2 a0 = *(const float2*)&As[kk][6 * ty + 0];
            float2 a1 = *(const float2*)&As[kk][6 * ty + 2];
            float2 a2 = *(const float2*)&As[kk][6 * ty + 4];
            float4 w0 = *(const float4*)&Vs[kk][tx * 8];
            float4 w1 = *(const float4*)&Vs[kk][tx * 8 + 4];
            const float av[6] = {a0.x, a0.y, a1.x, a1.y, a2.x, a2.y};
            const float wv[8] = {w0.x, w0.y, w0.z, w0.w, w1.x, w1.y, w1.z, w1.w};
            #pragma unroll
            for (int r = 0; r < 6; ++r)
                #pragma unroll
                for (int c = 0; c < 8; ++c)
                    acc[r][c] += av[r] * wv[c];
        }
        __syncthreads();
    }

    float* op = out + ((size_t)b * LSEQ + qt * 96 + 6 * ty) * DDIM + tx * 8;
    #pragma unroll
    for (int r = 0; r < 6; ++r) {
        float4 s0 = make_float4(acc[r][0], acc[r][1], acc[r][2], acc[r][3]);
        float4 s1 = make_float4(acc[r][4], acc[r][5], acc[r][6], acc[r][7]);
        *(float4*)(op + (size_t)r * DDIM)     = s0;
        *(float4*)(op + (size_t)r * DDIM + 4) = s1;
    }
}

// ---------------------------------------------------------------------------
extern "C" void kernel_launch(void* const* d_in, const int* in_sizes, int n_in,
                              void* d_out, int out_size)
{
    const float* q    = (const float*)d_in[0];
    const float* k    = (const float*)d_in[1];
    const float* v    = (const float*)d_in[2];
    const float* fc_w = (const float*)d_in[3];
    const float* fc_b = (const float*)d_in[4];

    float* out  = (float*)d_out;                                  // (B, L, D)
    float* attn = out + (size_t)BATCH * LSEQ * DDIM;              // (B, L, L)

    dim3 g1(LSEQ / 96, LSEQ / 96, BATCH);
    scores_kernel<<<g1, 256>>>(q, k, fc_w, fc_b, attn);

    softmax_kernel<<<BATCH * LSEQ, 256>>>(attn);

    dim3 g3(LSEQ / 96, BATCH);
    out_kernel<<<g3, 256>>>(attn, v, out);
}